// round 2
// baseline (speedup 1.0000x reference)
#include <cuda_runtime.h>

// Problem constants
#define NB 4
#define NL 1024
#define ND 768
#define NH 12
#define NHD 64
#define NSCALE 0.125f   // 64^-0.5

// Scratch (allocation-free rule: static __device__ arrays)
__device__ float g_Q[NB * NH * NL * NHD];
__device__ float g_K[NB * NH * NL * NHD];
__device__ float g_V[NB * NH * NL * NHD];
__device__ float g_O[NB * NL * ND];

// ---------------------------------------------------------------------------
// SGEMM: C[m,n] = sum_k A[m,k] * W[n,k] + bias[n]
// A row-major [M,768], W row-major [N,768] (K-contiguous both) -> "NT" gemm.
// BM=BN=128, BK=8, 256 threads, 8x8 fragment per thread.
// MODE 0: QKV projection epilogue -> scatter into g_Q (scaled) / g_K / g_V
// MODE 1: output projection epilogue -> write d_out
// ---------------------------------------------------------------------------
template <int MODE>
__global__ __launch_bounds__(256)
void sgemm_kernel(const float* __restrict__ A_in,
                  const float* __restrict__ W,
                  const float* __restrict__ bias,
                  float* __restrict__ out)
{
    constexpr int K = 768;
    constexpr int BM = 128, BN = 128, BK = 8;
    __shared__ float As[BK][BM];
    __shared__ float Bs[BK][BN];

    const float* A = (MODE == 1) ? (const float*)g_O : A_in;

    const int tid = threadIdx.x;
    const int tx = tid & 15;        // 0..15  -> N direction
    const int ty = tid >> 4;        // 0..15  -> M direction
    const int m0 = blockIdx.y * BM;
    const int n0 = blockIdx.x * BN;

    // loader mapping: 2 threads per row, float4 each (128 rows x 8 cols)
    const int lrow = tid >> 1;
    const int lc4  = (tid & 1) * 4;

    const float* Ap = A + (size_t)(m0 + lrow) * K + lc4;
    const float* Wp = W + (size_t)(n0 + lrow) * K + lc4;

    float acc[8][8];
#pragma unroll
    for (int i = 0; i < 8; i++)
#pragma unroll
        for (int j = 0; j < 8; j++) acc[i][j] = 0.f;

    for (int k0 = 0; k0 < K; k0 += BK) {
        float4 av = *(const float4*)(Ap + k0);
        float4 wv = *(const float4*)(Wp + k0);
        As[lc4 + 0][lrow] = av.x;
        As[lc4 + 1][lrow] = av.y;
        As[lc4 + 2][lrow] = av.z;
        As[lc4 + 3][lrow] = av.w;
        Bs[lc4 + 0][lrow] = wv.x;
        Bs[lc4 + 1][lrow] = wv.y;
        Bs[lc4 + 2][lrow] = wv.z;
        Bs[lc4 + 3][lrow] = wv.w;
        __syncthreads();

#pragma unroll
        for (int kk = 0; kk < BK; kk++) {
            float a[8], b[8];
            *(float4*)&a[0] = *(const float4*)&As[kk][ty * 8];
            *(float4*)&a[4] = *(const float4*)&As[kk][ty * 8 + 4];
            *(float4*)&b[0] = *(const float4*)&Bs[kk][tx * 8];
            *(float4*)&b[4] = *(const float4*)&Bs[kk][tx * 8 + 4];
#pragma unroll
            for (int i = 0; i < 8; i++)
#pragma unroll
                for (int j = 0; j < 8; j++)
                    acc[i][j] = fmaf(a[i], b[j], acc[i][j]);
        }
        __syncthreads();
    }

#pragma unroll
    for (int i = 0; i < 8; i++) {
        const int m = m0 + ty * 8 + i;
        const int b = m >> 10;          // / NL
        const int l = m & (NL - 1);
#pragma unroll
        for (int j = 0; j < 8; j++) {
            const int n = n0 + tx * 8 + j;
            float v = acc[i][j] + bias[n];
            if (MODE == 0) {
                if (n < ND) {
                    const int h = n >> 6, hd = n & 63;
                    g_Q[(((size_t)b * NH + h) * NL + l) * NHD + hd] = v * NSCALE;
                } else if (n < 2 * ND) {
                    const int nn = n - ND;
                    const int h = nn >> 6, hd = nn & 63;
                    g_K[(((size_t)b * NH + h) * NL + l) * NHD + hd] = v;
                } else {
                    const int nn = n - 2 * ND;
                    const int h = nn >> 6, hd = nn & 63;
                    g_V[(((size_t)b * NH + h) * NL + l) * NHD + hd] = v;
                }
            } else {
                out[(size_t)m * ND + n] = v;
            }
        }
    }
}

// ---------------------------------------------------------------------------
// Fused attention: per block = one (b,h) x 64 query rows; loops over 16 key
// tiles of 64. Online softmax (flash style), bias streamed straight from
// gmem into fragments. Thread map: 16x16, each thread owns a 4x4 fragment.
// smem: Qt [d][r], KP [d][c] (reused as P^T [c][r]), Vs [c][d]; all with a
// 4-float-group XOR swizzle so the transposed stores don't serialize.
// ---------------------------------------------------------------------------
__device__ __forceinline__ int swz(int row, int col)
{
    return row * 64 + ((((col >> 2) ^ (row & 15)) << 2) | (col & 3));
}

__global__ __launch_bounds__(256)
void attn_kernel(const float* __restrict__ bias)
{
    __shared__ float Qt[64 * 64];
    __shared__ float KP[64 * 64];
    __shared__ float Vs[64 * 64];

    const int tid = threadIdx.x;
    const int tx = tid & 15;   // key-col / out-dim group
    const int ty = tid >> 4;   // query-row group
    const int bh = blockIdx.y;           // 0..47
    const int b = bh / NH;
    const int h = bh - b * NH;
    const int q0 = blockIdx.x * 64;

    const float* Qg = g_Q + (size_t)(bh * NL + q0) * NHD;
    const float* Kg = g_K + (size_t)bh * NL * NHD;
    const float* Vg = g_V + (size_t)bh * NL * NHD;
    const float* Bg = bias + ((size_t)bh * NL + q0) * NL;

    // Load Q tile transposed into Qt[d][r]
#pragma unroll
    for (int u = 0; u < 4; u++) {
        const int f = tid + 256 * u;     // 0..1023 float4s
        const int r = f >> 4;
        const int d = (f & 15) * 4;
        float4 v = *(const float4*)(Qg + r * NHD + d);
        Qt[swz(d + 0, r)] = v.x;
        Qt[swz(d + 1, r)] = v.y;
        Qt[swz(d + 2, r)] = v.z;
        Qt[swz(d + 3, r)] = v.w;
    }

    float mrow[4], lrow[4], o[4][4];
#pragma unroll
    for (int i = 0; i < 4; i++) {
        mrow[i] = -1e30f;
        lrow[i] = 0.f;
#pragma unroll
        for (int j = 0; j < 4; j++) o[i][j] = 0.f;
    }

    for (int kt = 0; kt < 16; kt++) {
        const int kb = kt * 64;
        __syncthreads();   // previous tile's KP/Vs reads complete

        // Load K tile transposed (Kt[d][c]) and V tile natural (Vs[c][d])
#pragma unroll
        for (int u = 0; u < 4; u++) {
            const int f = tid + 256 * u;
            const int c = f >> 4;
            const int d4 = f & 15;
            const int d = d4 * 4;
            float4 kv = *(const float4*)(Kg + (size_t)(kb + c) * NHD + d);
            KP[swz(d + 0, c)] = kv.x;
            KP[swz(d + 1, c)] = kv.y;
            KP[swz(d + 2, c)] = kv.z;
            KP[swz(d + 3, c)] = kv.w;
            float4 vv = *(const float4*)(Vg + (size_t)(kb + c) * NHD + d);
            *(float4*)&Vs[c * 64 + ((d4 ^ (c & 15)) << 2)] = vv;
        }
        __syncthreads();

        // S = Q K^T + bias  (fragment 4x4 per thread)
        float s[4][4];
#pragma unroll
        for (int i = 0; i < 4; i++) {
            float4 bv = *(const float4*)(Bg + (size_t)(ty * 4 + i) * NL + kb + tx * 4);
            s[i][0] = bv.x; s[i][1] = bv.y; s[i][2] = bv.z; s[i][3] = bv.w;
        }
#pragma unroll 8
        for (int d = 0; d < 64; d++) {
            float4 qv = *(const float4*)&Qt[d * 64 + ((ty ^ (d & 15)) << 2)];
            float4 kv = *(const float4*)&KP[d * 64 + ((tx ^ (d & 15)) << 2)];
            const float qa[4] = {qv.x, qv.y, qv.z, qv.w};
            const float ka[4] = {kv.x, kv.y, kv.z, kv.w};
#pragma unroll
            for (int i = 0; i < 4; i++)
#pragma unroll
                for (int j = 0; j < 4; j++)
                    s[i][j] = fmaf(qa[i], ka[j], s[i][j]);
        }

        // Online softmax update; row spread over 16 lanes (tx) of same warp half
#pragma unroll
        for (int i = 0; i < 4; i++) {
            float mx = fmaxf(fmaxf(s[i][0], s[i][1]), fmaxf(s[i][2], s[i][3]));
#pragma unroll
            for (int off = 8; off > 0; off >>= 1)
                mx = fmaxf(mx, __shfl_xor_sync(0xffffffffu, mx, off));
            const float mnew = fmaxf(mrow[i], mx);
            const float corr = __expf(mrow[i] - mnew);
            mrow[i] = mnew;
            lrow[i] *= corr;
#pragma unroll
            for (int j = 0; j < 4; j++) o[i][j] *= corr;
            float ls = 0.f;
#pragma unroll
            for (int j = 0; j < 4; j++) {
                const float p = __expf(s[i][j] - mnew);
                s[i][j] = p;
                ls += p;
            }
            lrow[i] += ls;   // partial (this thread's 4 cols); reduced at end
        }

        __syncthreads();   // everyone done reading KP as K^T
        // Store P^T into KP: row = key col, col = query row
#pragma unroll
        for (int j = 0; j < 4; j++)
#pragma unroll
            for (int i = 0; i < 4; i++)
                KP[swz(tx * 4 + j, ty * 4 + i)] = s[i][j];
        __syncthreads();

        // O += P V
#pragma unroll 8
        for (int c = 0; c < 64; c++) {
            float4 pv = *(const float4*)&KP[c * 64 + ((ty ^ (c & 15)) << 2)];
            float4 vv = *(const float4*)&Vs[c * 64 + ((tx ^ (c & 15)) << 2)];
            const float pa[4] = {pv.x, pv.y, pv.z, pv.w};
            const float va[4] = {vv.x, vv.y, vv.z, vv.w};
#pragma unroll
            for (int i = 0; i < 4; i++)
#pragma unroll
                for (int j = 0; j < 4; j++)
                    o[i][j] = fmaf(pa[i], va[j], o[i][j]);
        }
    }

    // Finalize: reduce row sums across 16 lanes, normalize, write O[b,l,h*64+d]
#pragma unroll
    for (int i = 0; i < 4; i++) {
        float l = lrow[i];
#pragma unroll
        for (int off = 8; off > 0; off >>= 1)
            l += __shfl_xor_sync(0xffffffffu, l, off);
        const float inv = 1.0f / l;
        const int q = q0 + ty * 4 + i;
        float4 res = make_float4(o[i][0] * inv, o[i][1] * inv,
                                 o[i][2] * inv, o[i][3] * inv);
        *(float4*)(g_O + (size_t)(b * NL + q) * ND + h * NHD + tx * 4) = res;
    }
}

// ---------------------------------------------------------------------------
extern "C" void kernel_launch(void* const* d_in, const int* in_sizes, int n_in,
                              void* d_out, int out_size)
{
    (void)in_sizes; (void)n_in; (void)out_size;
    const float* x     = (const float*)d_in[0];
    const float* ab    = (const float*)d_in[1];
    const float* w_in  = (const float*)d_in[2];
    const float* b_in  = (const float*)d_in[3];
    const float* w_out = (const float*)d_in[4];
    const float* b_out = (const float*)d_in[5];
    float* out = (float*)d_out;

    // 1) QKV projection: [4096,768] x [2304,768]^T -> scatter Q(scaled)/K/V
    sgemm_kernel<0><<<dim3(2304 / 128, 4096 / 128), 256>>>(x, w_in, b_in, nullptr);
    // 2) Fused biased attention + softmax -> g_O [B,L,D]
    attn_kernel<<<dim3(NL / 64, NB * NH), 256>>>(ab);
    // 3) Output projection: [4096,768] x [768,768]^T + bias -> d_out
    sgemm_kernel<1><<<dim3(768 / 128, 4096 / 128), 256>>>(nullptr, w_out, b_out, out);
}